// round 11
// baseline (speedup 1.0000x reference)
#include <cuda_runtime.h>

#define TT   512
#define BB   2048
#define NTAG 16
#define LOG2E 1.4426950408889634f

// scratch: h sequence (T, B, 4) fp32 = 16.8 MB
__device__ float g_h[(size_t)TT * BB * 4];
// scratch: precomputed x-part of gate preactivations, [t][b][g][k] = 67 MB
__device__ float g_prex[(size_t)TT * BB * 16];

__device__ __forceinline__ float rcp_ap(float x)  { float r; asm("rcp.approx.f32 %0, %1;"  : "=f"(r) : "f"(x)); return r; }
__device__ __forceinline__ float ex2_ap(float x)  { float r; asm("ex2.approx.f32 %0, %1;"  : "=f"(r) : "f"(x)); return r; }
__device__ __forceinline__ float lg2_ap(float x)  { float r; asm("lg2.approx.f32 %0, %1;"  : "=f"(r) : "f"(x)); return r; }
__device__ __forceinline__ float cos_ap(float x)  { float r; asm("cos.approx.f32 %0, %1;"  : "=f"(r) : "f"(x)); return r; }

// Pade[5/4] tanh: tanh(u) = u*(q^2+105q+945)/(15q^2+420q+945), q=u^2.
// |err| <= ~5e-8 on |u|<=1 (gate inputs are products of cosines).
__device__ __forceinline__ float tanh_p54(float u) {
    float q = u * u;
    float n = fmaf(q + 105.0f, q, 945.0f) * u;
    float d = fmaf(fmaf(q, 15.0f, 420.0f), q, 945.0f);
    return n * rcp_ap(d);
}

// Pade[7/6] tanh: u*(q^3+378q^2+17325q+135135)/(28q^3+3150q^2+62370q+135135).
// |rel err| ~1e-5 at |u|=2.72 (cx range), far better below.
__device__ __forceinline__ float tanh_p76(float u) {
    float q  = u * u;
    float q2 = q * q;
    float n  = fmaf(q + 378.0f, q2, fmaf(17325.0f, q, 135135.0f));
    float d  = fmaf(fmaf(q, 28.0f, 3150.0f), q2, fmaf(62370.0f, q, 135135.0f));
    return u * n * rcp_ap(d);
}

// ---------------------------------------------------------------------------
// Kernel P: pre-pass. pre_x[t,b,g,k] = sum_d x[t,b,d]*wx[g,k,d] + th[g,k].
// (unchanged from R10: 21us, memory-bound on the 67MB prex write)
// ---------------------------------------------------------------------------
__global__ void __launch_bounds__(256)
pre_kernel(const float* __restrict__ x,
           const float* __restrict__ w_gates,
           const float* __restrict__ b_gates,
           const float* __restrict__ rx_theta)
{
    const int NQ = TT * BB / 4;
    int gt  = blockIdx.x * 256 + threadIdx.x;
    int p   = gt >> 2;
    int g   = gt & 3;

    float wx[4][8], th[4];
#pragma unroll
    for (int k = 0; k < 4; k++) {
        const float4* wr = (const float4*)(w_gates + g*48 + k*12);
        float4 w0 = wr[0], w1 = wr[1];
        wx[k][0]=w0.x; wx[k][1]=w0.y; wx[k][2]=w0.z; wx[k][3]=w0.w;
        wx[k][4]=w1.x; wx[k][5]=w1.y; wx[k][6]=w1.z; wx[k][7]=w1.w;
        th[k] = b_gates[g*4 + k] + rx_theta[g*4 + k];
    }

#pragma unroll
    for (int it = 0; it < 4; it++) {
        int row = p + it * NQ;
        const float4* xv4 = (const float4*)x + (size_t)row * 2;
        float4 A = xv4[0], B = xv4[1];
        float xv[8] = {A.x, A.y, A.z, A.w, B.x, B.y, B.z, B.w};

        float o[4];
#pragma unroll
        for (int k = 0; k < 4; k++) {
            float q = fmaf(xv[0], wx[k][0], th[k]);
            q = fmaf(xv[1], wx[k][1], q); q = fmaf(xv[2], wx[k][2], q);
            q = fmaf(xv[3], wx[k][3], q); q = fmaf(xv[4], wx[k][4], q);
            q = fmaf(xv[5], wx[k][5], q); q = fmaf(xv[6], wx[k][6], q);
            o[k] = fmaf(xv[7], wx[k][7], q);
        }
        ((float4*)g_prex)[(size_t)row * 4 + g] = make_float4(o[0], o[1], o[2], o[3]);
    }
}

// ---------------------------------------------------------------------------
// Kernel A: LSTM recurrence, 2 LANES PER CHAIN.
// Lane p owns gates {2p, 2p+1}: computes 8 pre, 8 cos, 8 gate values.
// ONE shfl_xor(1) stage (8 independent shfls) -> both lanes hold all 16 gate
// values; combine is replicated per lane (no h allgather). Chain ~185 cyc.
// ---------------------------------------------------------------------------
__global__ void __launch_bounds__(32, 1)
recur_kernel(const float* __restrict__ w_gates)
{
    const int tid = blockIdx.x * 32 + threadIdx.x;   // 0..4095
    const int b   = tid >> 1;                        // chain 0..2047
    const int p   = tid & 1;                         // lane within pair
    const bool P  = (p == 1);
    const int gA  = 2*p, gB = 2*p + 1;               // owned gates

    // recurrent weights for the two owned gates
    float whA[4][4], whB[4][4];
#pragma unroll
    for (int k = 0; k < 4; k++)
#pragma unroll
        for (int j = 0; j < 4; j++) {
            whA[k][j] = w_gates[gA*48 + k*12 + 8 + j];
            whB[k][j] = w_gates[gB*48 + k*12 + 8 + j];
        }

    // gate types: gate 2 = tanh, others sigmoid = 0.5 + 0.5*tanh(e/2)
    // (gm folded into c1 of the e-products)
    const float gmA = (gA == 2) ? 1.0f : 0.5f;
    const float gAA = (gA == 2) ? 1.0f : 0.5f;
    const float gBA = (gA == 2) ? 0.0f : 0.5f;
    const float gmB = 0.5f, gAB = 0.5f, gBB = 0.5f;  // gB in {1,3}: always sigmoid

    float h0 = 0.f, h1 = 0.f, h2 = 0.f, h3 = 0.f;
    float cx0 = 0.f, cx1 = 0.f, cx2 = 0.f, cx3 = 0.f;   // replicated per lane

    // 4-deep prefetch ring over pre_x; lane reads 2 float4 (gates gA, gB)
    const float4* pxp = (const float4*)g_prex;
    const size_t ofsA = (size_t)b * 4 + gA;
    const size_t ofsB = (size_t)b * 4 + gB;
    float4 pa[4], pb[4];
#pragma unroll
    for (int s = 0; s < 4; s++) {
        pa[s] = pxp[(size_t)s * (BB*4) + ofsA];
        pb[s] = pxp[(size_t)s * (BB*4) + ofsB];
    }

    float4* hout = (float4*)g_h;

#pragma unroll 2
    for (int t = 0; t < TT; t++) {
        const int slot = t & 3;
        float4 xA = pa[slot], xB = pb[slot];

        // ---- pre = prex + Wh·h ; c = cos(pre) for both owned gates ----
        float cA0, cA1, cA2, cA3, cB0, cB1, cB2, cB3;
        {
            float s0, s1;
            s0 = fmaf(h1, whA[0][1], fmaf(h0, whA[0][0], xA.x));
            s1 = fmaf(h3, whA[0][3], h2 * whA[0][2]);
            cA0 = cos_ap(s0 + s1);
            s0 = fmaf(h1, whA[1][1], fmaf(h0, whA[1][0], xA.y));
            s1 = fmaf(h3, whA[1][3], h2 * whA[1][2]);
            cA1 = cos_ap(s0 + s1);
            s0 = fmaf(h1, whA[2][1], fmaf(h0, whA[2][0], xA.z));
            s1 = fmaf(h3, whA[2][3], h2 * whA[2][2]);
            cA2 = cos_ap(s0 + s1);
            s0 = fmaf(h1, whA[3][1], fmaf(h0, whA[3][0], xA.w));
            s1 = fmaf(h3, whA[3][3], h2 * whA[3][2]);
            cA3 = cos_ap(s0 + s1);

            s0 = fmaf(h1, whB[0][1], fmaf(h0, whB[0][0], xB.x));
            s1 = fmaf(h3, whB[0][3], h2 * whB[0][2]);
            cB0 = cos_ap(s0 + s1);
            s0 = fmaf(h1, whB[1][1], fmaf(h0, whB[1][0], xB.y));
            s1 = fmaf(h3, whB[1][3], h2 * whB[1][2]);
            cB1 = cos_ap(s0 + s1);
            s0 = fmaf(h1, whB[2][1], fmaf(h0, whB[2][0], xB.z));
            s1 = fmaf(h3, whB[2][3], h2 * whB[2][2]);
            cB2 = cos_ap(s0 + s1);
            s0 = fmaf(h1, whB[3][1], fmaf(h0, whB[3][0], xB.w));
            s1 = fmaf(h3, whB[3][3], h2 * whB[3][2]);
            cB3 = cos_ap(s0 + s1);
        }

        // ---- off-path: refill ring slot with pre_x[t+4] ----
        {
            int tp = t + 4; if (tp > TT - 1) tp = TT - 1;
            pa[slot] = pxp[(size_t)tp * (BB*4) + ofsA];
            pb[slot] = pxp[(size_t)tp * (BB*4) + ofsB];
        }

        // ---- e-products per owned gate (gm folded into c1) ----
        float c1sA = gmA * cA1, c1sB = gmB * cB1;
        float t23A = cA2 * cA3,  t23B = cB2 * cB3;
        float uA1 = cA0 * c1sA,  uB1 = cB0 * c1sB;
        float uA0 = c1sA * t23A, uB0 = c1sB * t23B;
        float uA2 = uA1 * cA2,   uB2 = uB1 * cB2;
        float uA3 = uA1 * t23A,  uB3 = uB1 * t23B;

        // ---- gate values: v = fma(A, tanh_p54(u), B) ----
        float vA0 = fmaf(gAA, tanh_p54(uA0), gBA);
        float vA1 = fmaf(gAA, tanh_p54(uA1), gBA);
        float vA2 = fmaf(gAA, tanh_p54(uA2), gBA);
        float vA3 = fmaf(gAA, tanh_p54(uA3), gBA);
        float vB0 = fmaf(gAB, tanh_p54(uB0), gBB);
        float vB1 = fmaf(gAB, tanh_p54(uB1), gBB);
        float vB2 = fmaf(gAB, tanh_p54(uB2), gBB);
        float vB3 = fmaf(gAB, tanh_p54(uB3), gBB);

        // ---- ONE shfl stage: swap the 8 gate values with the pair partner ----
        float rA0 = __shfl_xor_sync(0xffffffffu, vA0, 1);
        float rA1 = __shfl_xor_sync(0xffffffffu, vA1, 1);
        float rA2 = __shfl_xor_sync(0xffffffffu, vA2, 1);
        float rA3 = __shfl_xor_sync(0xffffffffu, vA3, 1);
        float rB0 = __shfl_xor_sync(0xffffffffu, vB0, 1);
        float rB1 = __shfl_xor_sync(0xffffffffu, vB1, 1);
        float rB2 = __shfl_xor_sync(0xffffffffu, vB2, 1);
        float rB3 = __shfl_xor_sync(0xffffffffu, vB3, 1);

        // p=0 owns {f,i}, partner has {g,o}; p=1 owns {g,o}, partner {f,i}
        float F0 = P ? rA0 : vA0, F1 = P ? rA1 : vA1, F2 = P ? rA2 : vA2, F3 = P ? rA3 : vA3;
        float I0 = P ? rB0 : vB0, I1 = P ? rB1 : vB1, I2 = P ? rB2 : vB2, I3 = P ? rB3 : vB3;
        float G0 = P ? vA0 : rA0, G1 = P ? vA1 : rA1, G2 = P ? vA2 : rA2, G3 = P ? vA3 : rA3;
        float O0 = P ? vB0 : rB0, O1 = P ? vB1 : rB1, O2 = P ? vB2 : rB2, O3 = P ? vB3 : rB3;

        // ---- replicated combine (all 4 wires per lane; no allgather) ----
        cx0 = fmaf(F0, cx0, I0 * G0);
        cx1 = fmaf(F1, cx1, I1 * G1);
        cx2 = fmaf(F2, cx2, I2 * G2);
        cx3 = fmaf(F3, cx3, I3 * G3);
        h0 = O0 * tanh_p76(cx0);
        h1 = O1 * tanh_p76(cx1);
        h2 = O2 * tanh_p76(cx2);
        h3 = O3 * tanh_p76(cx3);

        if (p == 0)
            hout[(size_t)t * BB + b] = make_float4(h0, h1, h2, h3);
    }
}

// ---------------------------------------------------------------------------
// Kernel B: logits + log_softmax (unchanged from R10: 20us).
// ---------------------------------------------------------------------------
__global__ void __launch_bounds__(256)
out_kernel(const float* __restrict__ w_tag,
           const float* __restrict__ b_tag,
           float* __restrict__ out)
{
    const int NPAIR = TT * BB / 4;
    int gt   = blockIdx.x * 256 + threadIdx.x;
    int p    = gt >> 1;
    int half = gt & 1;

    const float4* wt = (const float4*)w_tag;
    float4 w[8];
#pragma unroll
    for (int j = 0; j < 8; j++) w[j] = wt[half*8 + j];
    float4 bta = ((const float4*)b_tag)[half*2];
    float4 btb = ((const float4*)b_tag)[half*2 + 1];
    float bt[8] = {bta.x, bta.y, bta.z, bta.w, btb.x, btb.y, btb.z, btb.w};

    const float4* hv4 = (const float4*)g_h;
    float4* o4 = (float4*)out;

#pragma unroll
    for (int it = 0; it < 4; it++) {
        int row = p + it * NPAIR;
        float4 hv = hv4[row];
        float lg[8];
#pragma unroll
        for (int j = 0; j < 8; j++)
            lg[j] = fmaf(w[j].w, hv.w, fmaf(w[j].z, hv.z, fmaf(w[j].y, hv.y, fmaf(w[j].x, hv.x, bt[j]))));

        float m = lg[0];
#pragma unroll
        for (int j = 1; j < 8; j++) m = fmaxf(m, lg[j]);
        m = fmaxf(m, __shfl_xor_sync(0xffffffffu, m, 1));

        float s = 0.f;
#pragma unroll
        for (int j = 0; j < 8; j++) s += ex2_ap((lg[j] - m) * LOG2E);
        s += __shfl_xor_sync(0xffffffffu, s, 1);

        float ls = fmaf(lg2_ap(s), 0.6931471805599453f, m);

        o4[(size_t)row*4 + half*2 + 0] = make_float4(lg[0]-ls, lg[1]-ls, lg[2]-ls, lg[3]-ls);
        o4[(size_t)row*4 + half*2 + 1] = make_float4(lg[4]-ls, lg[5]-ls, lg[6]-ls, lg[7]-ls);
    }
}

extern "C" void kernel_launch(void* const* d_in, const int* in_sizes, int n_in,
                              void* d_out, int out_size)
{
    const float* x        = (const float*)d_in[0];
    const float* w_gates  = (const float*)d_in[1];
    const float* b_gates  = (const float*)d_in[2];
    const float* rx_theta = (const float*)d_in[3];
    const float* w_tag    = (const float*)d_in[4];
    const float* b_tag    = (const float*)d_in[5];

    pre_kernel<<<4096, 256>>>(x, w_gates, b_gates, rx_theta);   // 4 rows / thread
    recur_kernel<<<128, 32>>>(w_gates);                          // 4096 threads, 2 lanes/chain
    out_kernel<<<2048, 256>>>(w_tag, b_tag, (float*)d_out);      // 4 rows / thread-pair
}

// round 12
// speedup vs baseline: 1.8428x; 1.8428x over previous
#include <cuda_runtime.h>

#define TT   512
#define BB   2048
#define NTAG 16
#define LOG2E 1.4426950408889634f

// scratch: h sequence (T, B, 4) fp32 = 16.8 MB
__device__ float g_h[(size_t)TT * BB * 4];

__device__ __forceinline__ float rcp_ap(float x)  { float r; asm("rcp.approx.f32 %0, %1;"  : "=f"(r) : "f"(x)); return r; }
__device__ __forceinline__ float ex2_ap(float x)  { float r; asm("ex2.approx.f32 %0, %1;"  : "=f"(r) : "f"(x)); return r; }
__device__ __forceinline__ float lg2_ap(float x)  { float r; asm("lg2.approx.f32 %0, %1;"  : "=f"(r) : "f"(x)); return r; }
__device__ __forceinline__ float cos_ap(float x)  { float r; asm("cos.approx.f32 %0, %1;"  : "=f"(r) : "f"(x)); return r; }

// Pade[7/6] tanh: u*(q^3+378q^2+17325q+135135)/(28q^3+3150q^2+62370q+135135),
// q=u^2. |rel err| ~1e-5 at |u|=2.72 (max |cx|), <<1e-6 on typical range.
// (validated in-bench R11: overall rel_err 6.08e-8)
__device__ __forceinline__ float tanh_p76(float u) {
    float q  = u * u;
    float q2 = q * q;
    float n  = fmaf(q + 378.0f, q2, fmaf(17325.0f, q, 135135.0f));
    float d  = fmaf(fmaf(q, 28.0f, 3150.0f), q2, fmaf(62370.0f, q, 135135.0f));
    return u * n * rcp_ap(d);
}

// ---------------------------------------------------------------------------
// Kernel A: the LSTM recurrence — exact R4 structure (best known, 132us):
// 4 lanes per chain (one per gate g), in-kernel x·W with 4-deep ring,
// exact ex2/rcp gate nonlinearity, 16-shfl gather, replicated combine,
// 256 blocks x 32 threads. ONLY change vs R4: combine tanh(cx) uses
// Pade[7/6] (1 rcp) instead of ex2+rcp — cuts MUFU 20->16 per lane-step.
// ---------------------------------------------------------------------------
__global__ void __launch_bounds__(32, 1)
recur_kernel(const float* __restrict__ x,
             const float* __restrict__ w_gates,
             const float* __restrict__ b_gates,
             const float* __restrict__ rx_theta)
{
    const int tid = blockIdx.x * 32 + threadIdx.x;   // 0..8191
    const int b   = tid >> 2;                        // batch chain 0..2047
    const int g   = tid & 3;                         // gate (f,i,g,o)

    // per-lane weights: w_gates layout (4,4,12): [g*48 + k*12 + d]
    float wx[4][8], wh[4][4], th[4];
#pragma unroll
    for (int k = 0; k < 4; k++) {
#pragma unroll
        for (int d = 0; d < 8; d++) wx[k][d] = w_gates[g*48 + k*12 + d];
#pragma unroll
        for (int j = 0; j < 4; j++) wh[k][j] = w_gates[g*48 + k*12 + 8 + j];
        th[k] = b_gates[g*4 + k] + rx_theta[g*4 + k];
    }
    // lane 2 is the tanh gate; lanes 0,1,3 are sigmoid gates
    const float gm = (g == 2) ?  2.0f * LOG2E : -LOG2E;
    const float gA = (g == 2) ? -2.0f         :  1.0f;
    const float gB = (g == 2) ?  1.0f         :  0.0f;

    float h0 = 0.f, h1 = 0.f, h2 = 0.f, h3 = 0.f;
    float cx[4] = {0.f, 0.f, 0.f, 0.f};

    const float4* xp = (const float4*)x;             // (t*BB + b)*2 indexing
    float4 xa[4], xb[4];                             // 4-deep prefetch ring
#pragma unroll
    for (int p = 0; p < 4; p++) {
        size_t i = ((size_t)p * BB + b) * 2;
        xa[p] = xp[i]; xb[p] = xp[i + 1];
    }

    // x-part of pre for t=0 (one step ahead); consumes slot 0
    float xacc[4];
    {
        float xv[8] = {xa[0].x, xa[0].y, xa[0].z, xa[0].w,
                       xb[0].x, xb[0].y, xb[0].z, xb[0].w};
#pragma unroll
        for (int k = 0; k < 4; k++) {
            float q = fmaf(xv[0], wx[k][0], th[k]);
            q = fmaf(xv[1], wx[k][1], q); q = fmaf(xv[2], wx[k][2], q);
            q = fmaf(xv[3], wx[k][3], q); q = fmaf(xv[4], wx[k][4], q);
            q = fmaf(xv[5], wx[k][5], q); q = fmaf(xv[6], wx[k][6], q);
            xacc[k] = fmaf(xv[7], wx[k][7], q);
        }
    }
    // slot 0 is next used at t=3 to build xacc(t=4) -> must hold x[4]
    {
        size_t i4 = ((size_t)4 * BB + b) * 2;
        xa[0] = xp[i4]; xb[0] = xp[i4 + 1];
    }

    float4* hout = (float4*)g_h;

#pragma unroll 4
    for (int t = 0; t < TT; t++) {
        // ---- pre = xacc + Wh·h ; c = cos(pre) (h-critical path) ----
        float c0, c1, c2, c3;
        {
            float s0, s1;
            s0 = fmaf(h1, wh[0][1], fmaf(h0, wh[0][0], xacc[0]));
            s1 = fmaf(h3, wh[0][3], h2 * wh[0][2]);
            c0 = cos_ap(s0 + s1);
            s0 = fmaf(h1, wh[1][1], fmaf(h0, wh[1][0], xacc[1]));
            s1 = fmaf(h3, wh[1][3], h2 * wh[1][2]);
            c1 = cos_ap(s0 + s1);
            s0 = fmaf(h1, wh[2][1], fmaf(h0, wh[2][0], xacc[2]));
            s1 = fmaf(h3, wh[2][3], h2 * wh[2][2]);
            c2 = cos_ap(s0 + s1);
            s0 = fmaf(h1, wh[3][1], fmaf(h0, wh[3][0], xacc[3]));
            s1 = fmaf(h3, wh[3][3], h2 * wh[3][2]);
            c3 = cos_ap(s0 + s1);
        }

        // ---- off-path: compute next step's x-part, then refill the ring ----
        {
            int slot = (t + 1) & 3;
            float xv[8] = {xa[slot].x, xa[slot].y, xa[slot].z, xa[slot].w,
                           xb[slot].x, xb[slot].y, xb[slot].z, xb[slot].w};
#pragma unroll
            for (int k = 0; k < 4; k++) {
                float q = fmaf(xv[0], wx[k][0], th[k]);
                q = fmaf(xv[1], wx[k][1], q); q = fmaf(xv[2], wx[k][2], q);
                q = fmaf(xv[3], wx[k][3], q); q = fmaf(xv[4], wx[k][4], q);
                q = fmaf(xv[5], wx[k][5], q); q = fmaf(xv[6], wx[k][6], q);
                xacc[k] = fmaf(xv[7], wx[k][7], q);
            }
            int tp = t + 5; if (tp > TT - 1) tp = TT - 1;
            size_t i = ((size_t)tp * BB + b) * 2;
            xa[slot] = xp[i]; xb[slot] = xp[i + 1];
        }

        // ---- expvals: e0=c1c2c3, e1=c0c1, e2=e1c2, e3=e1t23 ----
        float t23 = c2 * c3;
        float e1  = c0 * c1;
        float e0  = c1 * t23;
        float e2  = e1 * c2;
        float e3  = e1 * t23;

        // ---- gate nonlinearity (exact): v = fma(A, rcp(ex2(m*e)+1), B) ----
        float v0 = fmaf(gA, rcp_ap(ex2_ap(gm * e0) + 1.0f), gB);
        float v1 = fmaf(gA, rcp_ap(ex2_ap(gm * e1) + 1.0f), gB);
        float v2 = fmaf(gA, rcp_ap(ex2_ap(gm * e2) + 1.0f), gB);
        float v3 = fmaf(gA, rcp_ap(ex2_ap(gm * e3) + 1.0f), gB);

        // ---- gather all 4 gate vectors into every lane (16 independent shfl) ----
        float tg0[4], tg1[4], tg2[4], tg3[4];
#pragma unroll
        for (int s = 0; s < 4; s++) {
            tg0[s] = __shfl_sync(0xffffffffu, v0, s, 4);
            tg1[s] = __shfl_sync(0xffffffffu, v1, s, 4);
            tg2[s] = __shfl_sync(0xffffffffu, v2, s, 4);
            tg3[s] = __shfl_sync(0xffffffffu, v3, s, 4);
        }
        // tgK[s] = gate-s value for wire K. s: 0=f, 1=i, 2=g, 3=o.

        // ---- combine (replicated in all lanes); tanh(cx) via Pade[7/6] ----
        float hn[4];
#pragma unroll
        for (int k = 0; k < 4; k++) {
            float F = (k==0)?tg0[0]:(k==1)?tg1[0]:(k==2)?tg2[0]:tg3[0];
            float I = (k==0)?tg0[1]:(k==1)?tg1[1]:(k==2)?tg2[1]:tg3[1];
            float G = (k==0)?tg0[2]:(k==1)?tg1[2]:(k==2)?tg2[2]:tg3[2];
            float O = (k==0)?tg0[3]:(k==1)?tg1[3]:(k==2)?tg2[3]:tg3[3];
            float nc = fmaf(F, cx[k], I * G);
            cx[k] = nc;
            hn[k] = O * tanh_p76(nc);                    // o * tanh(cx)
        }
        h0 = hn[0]; h1 = hn[1]; h2 = hn[2]; h3 = hn[3];

        if (g == 0)
            hout[(size_t)t * BB + b] = make_float4(h0, h1, h2, h3);
    }
}

// ---------------------------------------------------------------------------
// Kernel B: logits + log_softmax (validated R8/R10 version, 20.4us).
// 2 threads per row-half (8 tags each), 4 rows per thread;
// softmax max/sum joined via shfl_xor within the lane pair.
// ---------------------------------------------------------------------------
__global__ void __launch_bounds__(256)
out_kernel(const float* __restrict__ w_tag,
           const float* __restrict__ b_tag,
           float* __restrict__ out)
{
    const int NPAIR = TT * BB / 4;               // 262144 rows per chunk
    int gt   = blockIdx.x * 256 + threadIdx.x;   // 0 .. 524287
    int p    = gt >> 1;                          // base row
    int half = gt & 1;

    const float4* wt = (const float4*)w_tag;     // 16 rows of float4
    float4 w[8];
#pragma unroll
    for (int j = 0; j < 8; j++) w[j] = wt[half*8 + j];
    float4 bta = ((const float4*)b_tag)[half*2];
    float4 btb = ((const float4*)b_tag)[half*2 + 1];
    float bt[8] = {bta.x, bta.y, bta.z, bta.w, btb.x, btb.y, btb.z, btb.w};

    const float4* hv4 = (const float4*)g_h;
    float4* o4 = (float4*)out;

#pragma unroll
    for (int it = 0; it < 4; it++) {
        int row = p + it * NPAIR;
        float4 hv = hv4[row];
        float lg[8];
#pragma unroll
        for (int j = 0; j < 8; j++)
            lg[j] = fmaf(w[j].w, hv.w, fmaf(w[j].z, hv.z, fmaf(w[j].y, hv.y, fmaf(w[j].x, hv.x, bt[j]))));

        float m = lg[0];
#pragma unroll
        for (int j = 1; j < 8; j++) m = fmaxf(m, lg[j]);
        m = fmaxf(m, __shfl_xor_sync(0xffffffffu, m, 1));

        float s = 0.f;
#pragma unroll
        for (int j = 0; j < 8; j++) s += ex2_ap((lg[j] - m) * LOG2E);
        s += __shfl_xor_sync(0xffffffffu, s, 1);

        float ls = fmaf(lg2_ap(s), 0.6931471805599453f, m);

        o4[(size_t)row*4 + half*2 + 0] = make_float4(lg[0]-ls, lg[1]-ls, lg[2]-ls, lg[3]-ls);
        o4[(size_t)row*4 + half*2 + 1] = make_float4(lg[4]-ls, lg[5]-ls, lg[6]-ls, lg[7]-ls);
    }
}

extern "C" void kernel_launch(void* const* d_in, const int* in_sizes, int n_in,
                              void* d_out, int out_size)
{
    const float* x        = (const float*)d_in[0];
    const float* w_gates  = (const float*)d_in[1];
    const float* b_gates  = (const float*)d_in[2];
    const float* rx_theta = (const float*)d_in[3];
    const float* w_tag    = (const float*)d_in[4];
    const float* b_tag    = (const float*)d_in[5];

    recur_kernel<<<256, 32>>>(x, w_gates, b_gates, rx_theta);   // R4 layout
    out_kernel<<<2048, 256>>>(w_tag, b_tag, (float*)d_out);     // 4 rows / thread-pair
}

// round 13
// speedup vs baseline: 1.8902x; 1.0257x over previous
#include <cuda_runtime.h>

#define TT   512
#define BB   2048
#define NTAG 16
#define LOG2E 1.4426950408889634f
#define LN2   0.6931471805599453f

__device__ __forceinline__ float rcp_ap(float x)  { float r; asm("rcp.approx.f32 %0, %1;"  : "=f"(r) : "f"(x)); return r; }
__device__ __forceinline__ float ex2_ap(float x)  { float r; asm("ex2.approx.f32 %0, %1;"  : "=f"(r) : "f"(x)); return r; }
__device__ __forceinline__ float lg2_ap(float x)  { float r; asm("lg2.approx.f32 %0, %1;"  : "=f"(r) : "f"(x)); return r; }
__device__ __forceinline__ float cos_ap(float x)  { float r; asm("cos.approx.f32 %0, %1;"  : "=f"(r) : "f"(x)); return r; }

// Pade[7/6] tanh (validated R11/R12): u*(q^3+378q^2+17325q+135135) /
// (28q^3+3150q^2+62370q+135135), q=u^2. |rel err| ~1e-5 at |u|=2.72.
__device__ __forceinline__ float tanh_p76(float u) {
    float q  = u * u;
    float q2 = q * q;
    float n  = fmaf(q + 378.0f, q2, fmaf(17325.0f, q, 135135.0f));
    float d  = fmaf(fmaf(q, 28.0f, 3150.0f), q2, fmaf(62370.0f, q, 135135.0f));
    return u * n * rcp_ap(d);
}

// ---------------------------------------------------------------------------
// Single fused kernel: LSTM recurrence + logits + log_softmax.
// Recurrence part is byte-identical to R12 (best known): 4 lanes per chain
// (one per gate g), in-kernel x·W with 4-deep ring, exact ex2/rcp gates,
// 16-shfl gather, replicated combine with Pade[7/6] tanh(cx).
// Epilogue per step (rides in the recurrence's issue bubbles): lane g owns
// tags [4g,4g+4); logits in log2 domain (LOG2E folded into w_tag/b_tag),
// softmax sum via 4 ex2 + 2 quad shfl-adds + 1 lg2; no max-shift needed
// (|logits| <= sum|w_tag| ~ 5, exp range safe in fp32). One STG.128/lane.
// ---------------------------------------------------------------------------
__global__ void __launch_bounds__(32, 1)
fused_kernel(const float* __restrict__ x,
             const float* __restrict__ w_gates,
             const float* __restrict__ b_gates,
             const float* __restrict__ rx_theta,
             const float* __restrict__ w_tag,
             const float* __restrict__ b_tag,
             float* __restrict__ out)
{
    const int tid = blockIdx.x * 32 + threadIdx.x;   // 0..8191
    const int b   = tid >> 2;                        // batch chain 0..2047
    const int g   = tid & 3;                         // gate (f,i,g,o)

    // per-lane gate weights: w_gates layout (4,4,12): [g*48 + k*12 + d]
    float wx[4][8], wh[4][4], th[4];
#pragma unroll
    for (int k = 0; k < 4; k++) {
#pragma unroll
        for (int d = 0; d < 8; d++) wx[k][d] = w_gates[g*48 + k*12 + d];
#pragma unroll
        for (int j = 0; j < 4; j++) wh[k][j] = w_gates[g*48 + k*12 + 8 + j];
        th[k] = b_gates[g*4 + k] + rx_theta[g*4 + k];
    }
    // lane 2 is the tanh gate; lanes 0,1,3 are sigmoid gates
    const float gm = (g == 2) ?  2.0f * LOG2E : -LOG2E;
    const float gA = (g == 2) ? -2.0f         :  1.0f;
    const float gB = (g == 2) ?  1.0f         :  0.0f;

    // per-lane tag weights (tags 4g..4g+3), prescaled by LOG2E (log2 domain)
    float4 wt[4]; float bt[4];
#pragma unroll
    for (int k = 0; k < 4; k++) {
        float4 w = ((const float4*)w_tag)[g*4 + k];
        wt[k] = make_float4(w.x * LOG2E, w.y * LOG2E, w.z * LOG2E, w.w * LOG2E);
        bt[k] = b_tag[g*4 + k] * LOG2E;
    }

    float h0 = 0.f, h1 = 0.f, h2 = 0.f, h3 = 0.f;
    float cx[4] = {0.f, 0.f, 0.f, 0.f};

    const float4* xp = (const float4*)x;             // (t*BB + b)*2 indexing
    float4 xa[4], xb[4];                             // 4-deep prefetch ring
#pragma unroll
    for (int p = 0; p < 4; p++) {
        size_t i = ((size_t)p * BB + b) * 2;
        xa[p] = xp[i]; xb[p] = xp[i + 1];
    }

    // x-part of pre for t=0 (one step ahead); consumes slot 0
    float xacc[4];
    {
        float xv[8] = {xa[0].x, xa[0].y, xa[0].z, xa[0].w,
                       xb[0].x, xb[0].y, xb[0].z, xb[0].w};
#pragma unroll
        for (int k = 0; k < 4; k++) {
            float q = fmaf(xv[0], wx[k][0], th[k]);
            q = fmaf(xv[1], wx[k][1], q); q = fmaf(xv[2], wx[k][2], q);
            q = fmaf(xv[3], wx[k][3], q); q = fmaf(xv[4], wx[k][4], q);
            q = fmaf(xv[5], wx[k][5], q); q = fmaf(xv[6], wx[k][6], q);
            xacc[k] = fmaf(xv[7], wx[k][7], q);
        }
    }
    // slot 0 is next used at t=3 to build xacc(t=4) -> must hold x[4]
    {
        size_t i4 = ((size_t)4 * BB + b) * 2;
        xa[0] = xp[i4]; xb[0] = xp[i4 + 1];
    }

    float4* op = (float4*)out;                       // row stride 4 float4s

#pragma unroll 4
    for (int t = 0; t < TT; t++) {
        // ---- pre = xacc + Wh·h ; c = cos(pre) (h-critical path) ----
        float c0, c1, c2, c3;
        {
            float s0, s1;
            s0 = fmaf(h1, wh[0][1], fmaf(h0, wh[0][0], xacc[0]));
            s1 = fmaf(h3, wh[0][3], h2 * wh[0][2]);
            c0 = cos_ap(s0 + s1);
            s0 = fmaf(h1, wh[1][1], fmaf(h0, wh[1][0], xacc[1]));
            s1 = fmaf(h3, wh[1][3], h2 * wh[1][2]);
            c1 = cos_ap(s0 + s1);
            s0 = fmaf(h1, wh[2][1], fmaf(h0, wh[2][0], xacc[2]));
            s1 = fmaf(h3, wh[2][3], h2 * wh[2][2]);
            c2 = cos_ap(s0 + s1);
            s0 = fmaf(h1, wh[3][1], fmaf(h0, wh[3][0], xacc[3]));
            s1 = fmaf(h3, wh[3][3], h2 * wh[3][2]);
            c3 = cos_ap(s0 + s1);
        }

        // ---- off-path: compute next step's x-part, then refill the ring ----
        {
            int slot = (t + 1) & 3;
            float xv[8] = {xa[slot].x, xa[slot].y, xa[slot].z, xa[slot].w,
                           xb[slot].x, xb[slot].y, xb[slot].z, xb[slot].w};
#pragma unroll
            for (int k = 0; k < 4; k++) {
                float q = fmaf(xv[0], wx[k][0], th[k]);
                q = fmaf(xv[1], wx[k][1], q); q = fmaf(xv[2], wx[k][2], q);
                q = fmaf(xv[3], wx[k][3], q); q = fmaf(xv[4], wx[k][4], q);
                q = fmaf(xv[5], wx[k][5], q); q = fmaf(xv[6], wx[k][6], q);
                xacc[k] = fmaf(xv[7], wx[k][7], q);
            }
            int tp = t + 5; if (tp > TT - 1) tp = TT - 1;
            size_t i = ((size_t)tp * BB + b) * 2;
            xa[slot] = xp[i]; xb[slot] = xp[i + 1];
        }

        // ---- expvals: e0=c1c2c3, e1=c0c1, e2=e1c2, e3=e1t23 ----
        float t23 = c2 * c3;
        float e1  = c0 * c1;
        float e0  = c1 * t23;
        float e2  = e1 * c2;
        float e3  = e1 * t23;

        // ---- gate nonlinearity (exact): v = fma(A, rcp(ex2(m*e)+1), B) ----
        float v0 = fmaf(gA, rcp_ap(ex2_ap(gm * e0) + 1.0f), gB);
        float v1 = fmaf(gA, rcp_ap(ex2_ap(gm * e1) + 1.0f), gB);
        float v2 = fmaf(gA, rcp_ap(ex2_ap(gm * e2) + 1.0f), gB);
        float v3 = fmaf(gA, rcp_ap(ex2_ap(gm * e3) + 1.0f), gB);

        // ---- gather all 4 gate vectors into every lane (16 independent shfl) ----
        float tg0[4], tg1[4], tg2[4], tg3[4];
#pragma unroll
        for (int s = 0; s < 4; s++) {
            tg0[s] = __shfl_sync(0xffffffffu, v0, s, 4);
            tg1[s] = __shfl_sync(0xffffffffu, v1, s, 4);
            tg2[s] = __shfl_sync(0xffffffffu, v2, s, 4);
            tg3[s] = __shfl_sync(0xffffffffu, v3, s, 4);
        }
        // tgK[s] = gate-s value for wire K. s: 0=f, 1=i, 2=g, 3=o.

        // ---- combine (replicated in all lanes); tanh(cx) via Pade[7/6] ----
        float hn[4];
#pragma unroll
        for (int k = 0; k < 4; k++) {
            float F = (k==0)?tg0[0]:(k==1)?tg1[0]:(k==2)?tg2[0]:tg3[0];
            float I = (k==0)?tg0[1]:(k==1)?tg1[1]:(k==2)?tg2[1]:tg3[1];
            float G = (k==0)?tg0[2]:(k==1)?tg1[2]:(k==2)?tg2[2]:tg3[2];
            float O = (k==0)?tg0[3]:(k==1)?tg1[3]:(k==2)?tg2[3]:tg3[3];
            float nc = fmaf(F, cx[k], I * G);
            cx[k] = nc;
            hn[k] = O * tanh_p76(nc);                    // o * tanh(cx)
        }
        h0 = hn[0]; h1 = hn[1]; h2 = hn[2]; h3 = hn[3];

        // ---- fused output epilogue (off the h-critical path) ----
        // log2-domain logits for this lane's 4 tags
        float l0 = fmaf(h3, wt[0].w, fmaf(h2, wt[0].z, fmaf(h1, wt[0].y, fmaf(h0, wt[0].x, bt[0]))));
        float l1 = fmaf(h3, wt[1].w, fmaf(h2, wt[1].z, fmaf(h1, wt[1].y, fmaf(h0, wt[1].x, bt[1]))));
        float l2 = fmaf(h3, wt[2].w, fmaf(h2, wt[2].z, fmaf(h1, wt[2].y, fmaf(h0, wt[2].x, bt[2]))));
        float l3 = fmaf(h3, wt[3].w, fmaf(h2, wt[3].z, fmaf(h1, wt[3].y, fmaf(h0, wt[3].x, bt[3]))));
        // softmax denominator across all 16 tags (quad tree-sum)
        float s4 = (ex2_ap(l0) + ex2_ap(l1)) + (ex2_ap(l2) + ex2_ap(l3));
        s4 += __shfl_xor_sync(0xffffffffu, s4, 1);
        s4 += __shfl_xor_sync(0xffffffffu, s4, 2);
        float lsl = lg2_ap(s4);
        // out = (lgl - lsl) * ln2  (natural-log log_softmax)
        float4 o = make_float4((l0 - lsl) * LN2, (l1 - lsl) * LN2,
                               (l2 - lsl) * LN2, (l3 - lsl) * LN2);
        op[((size_t)t * BB + b) * 4 + g] = o;
    }
}

extern "C" void kernel_launch(void* const* d_in, const int* in_sizes, int n_in,
                              void* d_out, int out_size)
{
    const float* x        = (const float*)d_in[0];
    const float* w_gates  = (const float*)d_in[1];
    const float* b_gates  = (const float*)d_in[2];
    const float* rx_theta = (const float*)d_in[3];
    const float* w_tag    = (const float*)d_in[4];
    const float* b_tag    = (const float*)d_in[5];

    fused_kernel<<<256, 32>>>(x, w_gates, b_gates, rx_theta,
                              w_tag, b_tag, (float*)d_out);
}